// round 1
// baseline (speedup 1.0000x reference)
#include <cuda_runtime.h>

#define FULL 0xFFFFFFFFu

// Problem shape (fixed): N=1, L=S=512, H=8, D=M=32
constexpr int L = 512;
constexpr int H = 8;
constexpr int NCHUNK = 16;            // s-chunks of 32 rows for matrix build
constexpr int MATS = 3 * 1024 + 32;   // KK(1024) SQQ(1024) KV(1024) Ksum(32)
constexpr float K_SCALE = 0.05892556509887896f; // 1/(3*sqrt(32))

// Scratch (no allocations allowed)
__device__ float g_Qn[L * H * 32];
__device__ float g_Kn[L * H * 32];
__device__ float g_part[NCHUNK * H * MATS];
__device__ float g_mats[H * MATS];

// ---------------------------------------------------------------------------
// Kernel 1: LayerNorm rows. Warp per row. Rows [0,4096) = Q, [4096,8192) = K.
// K rows additionally scaled by 1/(3*sqrt(D)) * key_lengths[s].
// ---------------------------------------------------------------------------
__global__ void ln_kernel(const float* __restrict__ q,
                          const float* __restrict__ k,
                          const float* __restrict__ klen) {
    int gw = (blockIdx.x * blockDim.x + threadIdx.x) >> 5;
    int lane = threadIdx.x & 31;
    bool isK = gw >= L * H;
    int row = isK ? gw - L * H : gw;            // row = l*H + h
    const float* src = isK ? k : q;
    float x = src[row * 32 + lane];
    float s = x, ss = x * x;
    #pragma unroll
    for (int o = 16; o; o >>= 1) {
        s  += __shfl_xor_sync(FULL, s,  o);
        ss += __shfl_xor_sync(FULL, ss, o);
    }
    float mu  = s * (1.0f / 32.0f);
    float var = fmaf(-mu, mu, ss * (1.0f / 32.0f));
    float y = (x - mu) * rsqrtf(var + 1e-5f);
    if (isK) y *= K_SCALE * klen[row >> 3];     // klen[s], s = row/H
    (isK ? g_Kn : g_Qn)[row * 32 + lane] = y;
}

// ---------------------------------------------------------------------------
// Kernel 2: per-(head, 32-row chunk) partial matrices:
//   KK[d][e]  = sum_s Kn[s][d]*Kn[s][e]
//   SQQ[d][e] = sum_l Qn[l][d]*Qn[l][e]
//   KV[m][d]  = sum_s Kn[s][d]*V[s][m]      (stored C[a=m][b=d] = V^T K)
//   Ksum[d]   = sum_s Kn[s][d]
// 256 threads: groups of 64 threads each own a matrix; thread computes a 4x4
// register tile via float4 LDS from padded (stride 36) smem tiles.
// ---------------------------------------------------------------------------
__global__ void mats_partial(const float* __restrict__ v) {
    __shared__ __align__(16) float sK[32][36];
    __shared__ __align__(16) float sQ[32][36];
    __shared__ __align__(16) float sV[32][36];
    int chunk = blockIdx.x, h = blockIdx.y;
    int tid = threadIdx.x;

    for (int i = tid; i < 1024; i += 256) {
        int r = i >> 5, c = i & 31;
        int g = ((chunk * 32 + r) * H + h) * 32 + c;
        sK[r][c] = g_Kn[g];
        sQ[r][c] = g_Qn[g];
        sV[r][c] = v[g];
    }
    __syncthreads();

    int grp = tid >> 6, t = tid & 63;
    float* outp = &g_part[(chunk * H + h) * MATS];

    if (grp < 3) {
        // C[a][b] = sum_r X[r][a] * Y[r][b]
        const float (*X)[36] = (grp == 0) ? sK : (grp == 1) ? sQ : sV;
        const float (*Y)[36] = (grp == 2) ? sK : X;
        int a0 = (t & 7) * 4, b0 = (t >> 3) * 4;
        float acc[4][4] = {};
        #pragma unroll 4
        for (int r = 0; r < 32; r++) {
            float4 xa = *(const float4*)&X[r][a0];
            float4 yb = *(const float4*)&Y[r][b0];
            float xs[4] = {xa.x, xa.y, xa.z, xa.w};
            float ys[4] = {yb.x, yb.y, yb.z, yb.w};
            #pragma unroll
            for (int i = 0; i < 4; i++)
                #pragma unroll
                for (int j = 0; j < 4; j++)
                    acc[i][j] = fmaf(xs[i], ys[j], acc[i][j]);
        }
        int base = grp * 1024;
        #pragma unroll
        for (int i = 0; i < 4; i++)
            #pragma unroll
            for (int j = 0; j < 4; j++)
                outp[base + (a0 + i) * 32 + (b0 + j)] = acc[i][j];
    } else if (t < 32) {
        float s = 0.0f;
        #pragma unroll
        for (int r = 0; r < 32; r++) s += sK[r][t];
        outp[3072 + t] = s;
    }
}

// ---------------------------------------------------------------------------
// Kernel 2b: deterministic reduce of the 16 chunk-partials per head.
// ---------------------------------------------------------------------------
__global__ void mats_reduce() {
    int idx = blockIdx.x * 256 + threadIdx.x;
    if (idx >= H * MATS) return;
    int h = idx / MATS, o = idx - h * MATS;
    float s = 0.0f;
    #pragma unroll
    for (int c = 0; c < NCHUNK; c++) s += g_part[(c * H + h) * MATS + o];
    g_mats[idx] = s;
}

// ---------------------------------------------------------------------------
// Kernel 3: epilogue, 1 warp per output row (l,h), lane = m = d index.
//   o1[m]   = sum_d Qn[l][d] * KV[m][d]
//   norm    = Qn[l].Ksum + 0.5 * Qn[l]^T KK Qn[l]
//   c       = 0.5 * Kn[l]^T SQQ Kn[l]
//   out[m]  = (o1[m] + c * V[l][m]) / norm
// ---------------------------------------------------------------------------
__global__ void final_kernel(const float* __restrict__ v,
                             float* __restrict__ out) {
    __shared__ float sKK[32][33];
    __shared__ float sQQ[32][33];
    __shared__ float sKV[32][33];
    __shared__ float sKsum[32];
    int h = blockIdx.y;
    int tid = threadIdx.x, lane = tid & 31, w = tid >> 5;
    const float* m = &g_mats[h * MATS];

    for (int i = tid; i < 1024; i += 256) {
        int r = i >> 5, c = i & 31;
        sKK[r][c] = m[i];
        sQQ[r][c] = m[1024 + i];
        sKV[r][c] = m[2048 + i];
    }
    if (tid < 32) sKsum[tid] = m[3072 + tid];
    __syncthreads();

    int l = blockIdx.x * 8 + w;
    int g = (l * H + h) * 32 + lane;
    float q = g_Qn[g], k = g_Kn[g], vv = v[g];

    float o1 = 0.0f, wq = 0.0f, wk = 0.0f;
    #pragma unroll
    for (int d = 0; d < 32; d++) {
        float qd = __shfl_sync(FULL, q, d);
        float kd = __shfl_sync(FULL, k, d);
        o1 = fmaf(qd, sKV[lane][d], o1);   // banks (lane+d)%32: clean
        wq = fmaf(qd, sKK[d][lane], wq);   // banks (d+lane)%32: clean
        wk = fmaf(kd, sQQ[d][lane], wk);
    }
    float tn = fmaf(0.5f * wq, q, q * sKsum[lane]);  // per-lane norm partial
    float tc = wk * k;                                // per-lane c partial
    #pragma unroll
    for (int o = 16; o; o >>= 1) {
        tn += __shfl_xor_sync(FULL, tn, o);
        tc += __shfl_xor_sync(FULL, tc, o);
    }
    out[g] = (o1 + 0.5f * tc * vv) / tn;
}

// ---------------------------------------------------------------------------
extern "C" void kernel_launch(void* const* d_in, const int* in_sizes, int n_in,
                              void* d_out, int out_size) {
    const float* q    = (const float*)d_in[0];
    const float* k    = (const float*)d_in[1];
    const float* v    = (const float*)d_in[2];
    // d_in[3] attn_mask, d_in[4] query_lengths: unused by the reference
    const float* klen = (const float*)d_in[5];
    float* out = (float*)d_out;

    ln_kernel<<<(2 * L * H * 32) / 256, 256>>>(q, k, klen);      // 8192 warps
    mats_partial<<<dim3(NCHUNK, H), 256>>>(v);
    mats_reduce<<<(H * MATS + 255) / 256, 256>>>();
    final_kernel<<<dim3(L / 8, H), 256>>>(v, out);
}